// round 6
// baseline (speedup 1.0000x reference)
#include <cuda_runtime.h>
#include <cuda_fp16.h>
#include <math.h>

#define V 50257
#define H 1024
#define T 10
#define LROWS 16
#define NLB ((V + LROWS - 1) / LROWS)   // 3142 logits blocks

// ---------------- device scratch (no allocations allowed) ----------------
__device__ __align__(16) float g_h[2][H];
__device__ __align__(16) float g_c[2][H];
__device__ __align__(16) float g_enc[T * H];
__device__ __align__(16) float g_prev[H];
__device__ __align__(16) float g_q[H];
__device__ __align__(16) float g_ctx[H];
__device__ int   g_tok[T];
__device__ float g_pval[2 * NLB + 32];   // top-2 per block
__device__ int   g_pidx[2 * NLB + 32];
__device__ unsigned int g_cnt1;
__device__ unsigned int g_cnt2;
__device__ int   g_wmax_bits;            // global max|out_w| as int bits
__device__ __align__(16) __half g_w16[(size_t)V * H];   // fp16 out_w (~98MB, L2-resident)

__device__ __forceinline__ float sigm(float x) { return 1.f / (1.f + expf(-x)); }
__device__ __forceinline__ float dot4(float4 a, float4 b) {
    return a.x * b.x + a.y * b.y + a.z * b.z + a.w * b.w;
}

// ---------------- init: decode tokens (int64 vs int32), zero state/out ---
__global__ void k_init(const void* __restrict__ seq_raw,
                       float* __restrict__ out, int out_size) {
    int tid = blockIdx.x * blockDim.x + threadIdx.x;
    if (tid == 0) {
        const long long* s64 = (const long long*)seq_raw;
        bool ok64 = true;
        for (int i = 0; i < T; i++) {
            long long v = s64[i];
            if (v < 0 || v >= V) { ok64 = false; break; }
        }
        const int* s32 = (const int*)seq_raw;
        for (int i = 0; i < T; i++) g_tok[i] = ok64 ? (int)s64[i] : s32[i];
        g_cnt1 = 0; g_cnt2 = 0; g_wmax_bits = 0;
    }
    int stride = gridDim.x * blockDim.x;
    for (int i = tid; i < H; i += stride) {
        g_h[0][i] = 0.f; g_c[0][i] = 0.f; g_prev[i] = 0.f;
    }
    for (int i = tid; i < out_size; i += stride) out[i] = 0.f;
}

// ---------------- encoder LSTM: 2 units/block, warp-per-gate -------------
__global__ void k_lstm_enc(const float* __restrict__ w_ih,
                           const float* __restrict__ w_hh,
                           const float* __restrict__ b_ih,
                           const float* __restrict__ b_hh,
                           const float* __restrict__ embeds,
                           int step, int bi) {
    int tid  = threadIdx.x;
    int warp = tid >> 5;
    int lane = tid & 31;
    int j    = blockIdx.x * 2 + (warp >> 2);
    int gate = warp & 3;

    const float4* x4 = (const float4*)(embeds + (size_t)g_tok[step] * H);
    const float4* h4 = (const float4*)g_h[bi];
    const float4* wi = (const float4*)w_ih + (size_t)(gate * H + j) * 256;
    const float4* wh = (const float4*)w_hh + (size_t)(gate * H + j) * 256;

    float acc = 0.f;
#pragma unroll
    for (int i = 0; i < 8; i++) {
        int k = lane + 32 * i;
        acc += dot4(wi[k], x4[k]) + dot4(wh[k], h4[k]);
    }
    for (int off = 16; off > 0; off >>= 1)
        acc += __shfl_down_sync(0xffffffffu, acc, off);

    __shared__ float s[8];
    if (lane == 0) s[warp] = acc;
    __syncthreads();
    if (tid < 2) {
        int u = blockIdx.x * 2 + tid;
        float gi = s[tid * 4 + 0] + b_ih[u]         + b_hh[u];
        float gf = s[tid * 4 + 1] + b_ih[H + u]     + b_hh[H + u];
        float gg = s[tid * 4 + 2] + b_ih[2 * H + u] + b_hh[2 * H + u];
        float go = s[tid * 4 + 3] + b_ih[3 * H + u] + b_hh[3 * H + u];
        float i_ = sigm(gi), f_ = sigm(gf), g_ = tanhf(gg), o_ = sigm(go);
        float cn = f_ * g_c[bi][u] + i_ * g_;
        float hn = o_ * tanhf(cn);
        g_c[1 - bi][u] = cn;
        g_h[1 - bi][u] = hn;
        g_enc[step * H + u] = hn;
    }
}

// ---------------- q = wa^T h, then last block does softmax+ctx -----------
__global__ void k_qattn(const float* __restrict__ wa, int bi) {
    int tid  = threadIdx.x;
    int lane = tid & 31;
    int warp = tid >> 5;
    int col  = blockIdx.x * 32 + lane;
    const float* h = g_h[bi];

    float acc = 0.f;
    for (int i = warp; i < H; i += 8) acc += h[i] * wa[(size_t)i * H + col];
    __shared__ float s[256];
    s[tid] = acc;
    __syncthreads();
    for (int off = 128; off >= 32; off >>= 1) {
        if (tid < off) s[tid] += s[tid + off];
        __syncthreads();
    }
    if (tid < 32) g_q[col] = s[tid];

    __shared__ int s_last;
    __threadfence();
    if (tid == 0) s_last = (atomicAdd(&g_cnt1, 1u) == gridDim.x - 1);
    __syncthreads();
    if (!s_last) return;
    if (tid == 0) g_cnt1 = 0;

    float at[T];
#pragma unroll
    for (int t = 0; t < T; t++) at[t] = 0.f;
    for (int k = tid; k < H; k += 256) {
        float qv = g_q[k];
#pragma unroll
        for (int t = 0; t < T; t++) at[t] += qv * g_enc[t * H + k];
    }
#pragma unroll
    for (int t = 0; t < T; t++)
        for (int off = 16; off > 0; off >>= 1)
            at[t] += __shfl_down_sync(0xffffffffu, at[t], off);
    __shared__ float s2[T * 8];
    if (lane == 0) {
#pragma unroll
        for (int t = 0; t < T; t++) s2[t * 8 + warp] = at[t];
    }
    __syncthreads();
    __shared__ float sa[T];
    if (tid == 0) {
        float sc[T];
        float m = -INFINITY;
#pragma unroll
        for (int t = 0; t < T; t++) {
            float v = 0.f;
#pragma unroll
            for (int w = 0; w < 8; w++) v += s2[t * 8 + w];
            sc[t] = v;
            m = fmaxf(m, v);
        }
        float sum = 0.f;
#pragma unroll
        for (int t = 0; t < T; t++) { float e = expf(sc[t] - m); sa[t] = e; sum += e; }
#pragma unroll
        for (int t = 0; t < T; t++) sa[t] /= sum;
    }
    __syncthreads();
    for (int k = tid; k < H; k += 256) {
        float v = 0.f;
#pragma unroll
        for (int t = 0; t < T; t++) v += sa[t] * g_enc[t * H + k];
        g_ctx[k] = v;
    }
}

// ---------------- decoder LSTM: 2 units/block, warp-per-gate -------------
__global__ void k_lstm_dec(const float* __restrict__ w_ih,
                           const float* __restrict__ w_hh,
                           const float* __restrict__ b_ih,
                           const float* __restrict__ b_hh,
                           int bi) {
    int tid  = threadIdx.x;
    int warp = tid >> 5;
    int lane = tid & 31;
    int j    = blockIdx.x * 2 + (warp >> 2);
    int gate = warp & 3;

    const float4* h4 = (const float4*)g_h[bi];
    const float4* p4 = (const float4*)g_prev;
    const float4* c4 = (const float4*)g_ctx;
    const float4* wi = (const float4*)w_ih + (size_t)(gate * H + j) * 512;
    const float4* wh = (const float4*)w_hh + (size_t)(gate * H + j) * 256;

    float acc = 0.f;
#pragma unroll
    for (int i = 0; i < 8; i++) {
        int k = lane + 32 * i;
        float4 xa = p4[k];
        xa.x = fmaxf(xa.x, 0.f); xa.y = fmaxf(xa.y, 0.f);
        xa.z = fmaxf(xa.z, 0.f); xa.w = fmaxf(xa.w, 0.f);
        acc += dot4(wi[k], xa);
        acc += dot4(wi[256 + k], c4[k]);
        acc += dot4(wh[k], h4[k]);
    }
    for (int off = 16; off > 0; off >>= 1)
        acc += __shfl_down_sync(0xffffffffu, acc, off);

    __shared__ float s[8];
    if (lane == 0) s[warp] = acc;
    __syncthreads();
    if (tid < 2) {
        int u = blockIdx.x * 2 + tid;
        float gi = s[tid * 4 + 0] + b_ih[u]         + b_hh[u];
        float gf = s[tid * 4 + 1] + b_ih[H + u]     + b_hh[H + u];
        float gg = s[tid * 4 + 2] + b_ih[2 * H + u] + b_hh[2 * H + u];
        float go = s[tid * 4 + 3] + b_ih[3 * H + u] + b_hh[3 * H + u];
        float i_ = sigm(gi), f_ = sigm(gf), g_ = tanhf(gg), o_ = sigm(go);
        float cn = f_ * g_c[bi][u] + i_ * g_;
        float hn = o_ * tanhf(cn);
        g_c[1 - bi][u] = cn;
        g_h[1 - bi][u] = hn;
    }
}

// ------- shared final-argmax tail (runs in the last logits block) --------
// B (fp16 error bound) derived analytically: u * max|w| * ||h||_1.
// Collects all per-block top-2 entries within 2B of approx max, recomputes
// them exactly in fp32, picks the first-index max (== jnp.argmax on fp32).
__device__ __forceinline__ void final_argmax_tail(
        const float* __restrict__ w32, const float* __restrict__ out_b,
        int hb, const float* __restrict__ embeds,
        float* __restrict__ out_ids, int write_ids, int step, int nb,
        int use_bound) {
    int tid  = threadIdx.x;
    int lane = tid & 31;
    int warp = tid >> 5;

    // ||h||_1 (only needed when use_bound)
    __shared__ float s_h1;
    if (use_bound) {
        float h1 = 0.f;
        for (int k = tid; k < H; k += 256) h1 += fabsf(g_h[hb][k]);
        for (int off = 16; off > 0; off >>= 1)
            h1 += __shfl_down_sync(0xffffffffu, h1, off);
        __shared__ float sh[8];
        if (lane == 0) sh[warp] = h1;
        __syncthreads();
        if (tid == 0) {
            float v = 0.f;
#pragma unroll
            for (int w = 0; w < 8; w++) v += sh[w];
            s_h1 = v;
        }
        __syncthreads();
    }
    float B = use_bound
            ? 6.5e-4f * __int_as_float(g_wmax_bits) * s_h1 + 1e-6f
            : 0.f;

    float best = -INFINITY; int bidx = 0x7fffffff;
    for (int i = tid; i < 2 * nb; i += 256) {
        float v = g_pval[i]; int ix = g_pidx[i];
        if (v > best || (v == best && ix < bidx)) { best = v; bidx = ix; }
    }
    __shared__ float sv[256]; __shared__ int si[256];
    sv[tid] = best; si[tid] = bidx;
    __syncthreads();
    for (int off = 128; off > 0; off >>= 1) {
        if (tid < off) {
            float v2 = sv[tid + off]; int i2 = si[tid + off];
            if (v2 > sv[tid] || (v2 == sv[tid] && i2 < si[tid])) { sv[tid] = v2; si[tid] = i2; }
        }
        __syncthreads();
    }
    float thresh = sv[0] - 2.f * B;

    __shared__ int cand[64];
    __shared__ int s_nc;
    __shared__ float cval[64];
    if (tid == 0) s_nc = 0;
    __syncthreads();
    for (int i = tid; i < 2 * nb; i += 256) {
        if (g_pval[i] >= thresh && g_pidx[i] < V) {
            int slot = atomicAdd(&s_nc, 1);
            if (slot < 64) cand[slot] = g_pidx[i];
        }
    }
    __syncthreads();
    int nc = min(s_nc, 64);

    const float4* h4f = (const float4*)g_h[hb];
    for (int c = warp; c < nc; c += 8) {
        int r = cand[c];
        const float4* wr = (const float4*)(w32 + (size_t)r * H);
        float acc = 0.f;
#pragma unroll
        for (int i = 0; i < 8; i++) {
            int k = lane + 32 * i;
            acc += dot4(wr[k], h4f[k]);
        }
        for (int off = 16; off > 0; off >>= 1)
            acc += __shfl_down_sync(0xffffffffu, acc, off);
        if (lane == 0) cval[c] = acc + out_b[r];
    }
    __syncthreads();
    __shared__ int s_idx;
    if (tid == 0) {
        float bv2 = -INFINITY; int bi2 = 0x7fffffff;
        for (int c = 0; c < nc; c++) {
            if (cval[c] > bv2 || (cval[c] == bv2 && cand[c] < bi2)) {
                bv2 = cval[c]; bi2 = cand[c];
            }
        }
        s_idx = bi2;
    }
    __syncthreads();
    int idx = s_idx;
    for (int k = tid; k < H; k += 256)
        g_prev[k] = embeds[(size_t)idx * H + k];
    if (tid == 0 && write_ids) out_ids[step] = (float)idx;
}

__device__ __forceinline__ void publish_block_top2(
        int tid, const float* bv, const int* bix,
        int blockId, int nblocks, int* s_last) {
    if (tid == 0) {
        float v1 = -INFINITY, v2 = -INFINITY; int i1 = 0x7fffffff, i2 = 0x7fffffff;
#pragma unroll
        for (int w = 0; w < 16; w++) {
            float v = bv[w]; int ix = bix[w];
            if (v > v1 || (v == v1 && ix < i1)) { v2 = v1; i2 = i1; v1 = v; i1 = ix; }
            else if (v > v2 || (v == v2 && ix < i2)) { v2 = v; i2 = ix; }
        }
        g_pval[2 * blockId] = v1;     g_pidx[2 * blockId] = i1;
        g_pval[2 * blockId + 1] = v2; g_pidx[2 * blockId + 1] = i2;
        __threadfence();
        *s_last = (atomicAdd(&g_cnt2, 1u) == nblocks - 1);
    }
}

// ------- step 0: fp32 logits (exact) + write fp16 copy + max|w| ----------
__global__ void k_logits_conv(const float* __restrict__ w32,
                              const float* __restrict__ out_b,
                              int hb, float* __restrict__ out,
                              const float* __restrict__ embeds,
                              float* __restrict__ out_ids, int write_ids, int step) {
    int tid  = threadIdx.x;
    int lane = tid & 31;
    int warp = tid >> 5;
    int r0 = blockIdx.x * LROWS + warp * 2;

    const float4* h4 = (const float4*)g_h[hb];
    float4 hreg[8];
#pragma unroll
    for (int i = 0; i < 4; i++) {
        int c = lane + 32 * i;
        hreg[2 * i]     = h4[2 * c];
        hreg[2 * i + 1] = h4[2 * c + 1];
    }

    float a0 = 0.f, a1 = 0.f, wm = 0.f;
#pragma unroll
    for (int row = 0; row < 2; row++) {
        int r = r0 + row;
        if (r >= V) break;
        const float4* wr = (const float4*)(w32 + (size_t)r * H);
        uint4* w16 = (uint4*)(g_w16 + (size_t)r * H);
        float acc = 0.f;
#pragma unroll
        for (int i = 0; i < 4; i++) {
            int c = lane + 32 * i;
            float4 wa4 = __ldcs(wr + 2 * c);
            float4 wb4 = __ldcs(wr + 2 * c + 1);
            acc += dot4(wa4, hreg[2 * i]) + dot4(wb4, hreg[2 * i + 1]);
            wm = fmaxf(wm, fmaxf(fmaxf(fabsf(wa4.x), fabsf(wa4.y)),
                                 fmaxf(fabsf(wa4.z), fabsf(wa4.w))));
            wm = fmaxf(wm, fmaxf(fmaxf(fabsf(wb4.x), fabsf(wb4.y)),
                                 fmaxf(fabsf(wb4.z), fabsf(wb4.w))));
            __half2 p0 = __floats2half2_rn(wa4.x, wa4.y);
            __half2 p1 = __floats2half2_rn(wa4.z, wa4.w);
            __half2 p2 = __floats2half2_rn(wb4.x, wb4.y);
            __half2 p3 = __floats2half2_rn(wb4.z, wb4.w);
            uint4 pk;
            pk.x = *(unsigned int*)&p0; pk.y = *(unsigned int*)&p1;
            pk.z = *(unsigned int*)&p2; pk.w = *(unsigned int*)&p3;
            w16[c] = pk;          // plain store: keep fp16 copy in L2
        }
        if (row == 0) a0 = acc; else a1 = acc;
    }
    for (int off = 16; off > 0; off >>= 1) {
        a0 += __shfl_down_sync(0xffffffffu, a0, off);
        a1 += __shfl_down_sync(0xffffffffu, a1, off);
        wm = fmaxf(wm, __shfl_down_sync(0xffffffffu, wm, off));
    }

    __shared__ float bv[16];
    __shared__ int   bix[16];
    __shared__ float swm[8];
    __shared__ int   s_last;
    if (lane == 0) {
        int r1 = r0 + 1;
        float l0 = -INFINITY, l1 = -INFINITY;
        if (r0 < V) { l0 = a0 + out_b[r0]; __stcs(out + r0, l0); }
        if (r1 < V) { l1 = a1 + out_b[r1]; __stcs(out + r1, l1); }
        bv[warp * 2] = l0;     bix[warp * 2] = r0;
        bv[warp * 2 + 1] = l1; bix[warp * 2 + 1] = r1;
        swm[warp] = wm;
    }
    __syncthreads();
    if (tid == 0) {
        float m = 0.f;
#pragma unroll
        for (int w = 0; w < 8; w++) m = fmaxf(m, swm[w]);
        atomicMax(&g_wmax_bits, __float_as_int(m));
    }
    publish_block_top2(tid, bv, bix, blockIdx.x, gridDim.x, &s_last);
    __syncthreads();
    if (!s_last) return;
    if (tid == 0) g_cnt2 = 0;
    final_argmax_tail(w32, out_b, hb, embeds, out_ids, write_ids, step,
                      gridDim.x, /*use_bound=*/0);
}

// ------- steps 1..9: fp16 logits (lean loop) + bounded exact argmax ------
__global__ void k_logits16(const float* __restrict__ w32,
                           const float* __restrict__ out_b,
                           int hb, float* __restrict__ out,
                           const float* __restrict__ embeds,
                           float* __restrict__ out_ids, int write_ids, int step) {
    int tid  = threadIdx.x;
    int lane = tid & 31;
    int warp = tid >> 5;
    int r0 = blockIdx.x * LROWS + warp * 2;
    int r1 = r0 + 1;

    const float4* h4 = (const float4*)g_h[hb];
    float4 hreg[8];
#pragma unroll
    for (int i = 0; i < 4; i++) {
        int c = lane + 32 * i;
        hreg[2 * i]     = h4[2 * c];
        hreg[2 * i + 1] = h4[2 * c + 1];
    }

    float a0 = 0.f, a1 = 0.f;
#pragma unroll
    for (int row = 0; row < 2; row++) {
        int r = r0 + row;
        if (r >= V) break;
        const uint4* wr = (const uint4*)(g_w16 + (size_t)r * H);
        float acc = 0.f;
#pragma unroll
        for (int i = 0; i < 4; i++) {
            uint4 u = wr[lane + 32 * i];          // plain load: L2-resident
            float4 ha = hreg[2 * i], hb2 = hreg[2 * i + 1];
            float2 f;
            f = __half22float2(*(const __half2*)&u.x);
            acc += f.x * ha.x + f.y * ha.y;
            f = __half22float2(*(const __half2*)&u.y);
            acc += f.x * ha.z + f.y * ha.w;
            f = __half22float2(*(const __half2*)&u.z);
            acc += f.x * hb2.x + f.y * hb2.y;
            f = __half22float2(*(const __half2*)&u.w);
            acc += f.x * hb2.z + f.y * hb2.w;
        }
        if (row == 0) a0 = acc; else a1 = acc;
    }
    for (int off = 16; off > 0; off >>= 1) {
        a0 += __shfl_down_sync(0xffffffffu, a0, off);
        a1 += __shfl_down_sync(0xffffffffu, a1, off);
    }

    __shared__ float bv[16];
    __shared__ int   bix[16];
    __shared__ int   s_last;
    if (lane == 0) {
        float l0 = -INFINITY, l1 = -INFINITY;
        if (r0 < V) { l0 = a0 + out_b[r0]; __stcs(out + r0, l0); }
        if (r1 < V) { l1 = a1 + out_b[r1]; __stcs(out + r1, l1); }
        bv[warp * 2] = l0;     bix[warp * 2] = r0;
        bv[warp * 2 + 1] = l1; bix[warp * 2 + 1] = r1;
    }
    __syncthreads();
    publish_block_top2(tid, bv, bix, blockIdx.x, gridDim.x, &s_last);
    __syncthreads();
    if (!s_last) return;
    if (tid == 0) g_cnt2 = 0;
    final_argmax_tail(w32, out_b, hb, embeds, out_ids, write_ids, step,
                      gridDim.x, /*use_bound=*/1);
}

// ---------------- launch ---------------------------------------------------
extern "C" void kernel_launch(void* const* d_in, const int* in_sizes, int n_in,
                              void* d_out, int out_size) {
    const void*  seq    = d_in[0];
    const float* embeds = (const float*)d_in[1];
    const float* ew_ih  = (const float*)d_in[2];
    const float* ew_hh  = (const float*)d_in[3];
    const float* eb_ih  = (const float*)d_in[4];
    const float* eb_hh  = (const float*)d_in[5];
    const float* dw_ih  = (const float*)d_in[6];
    const float* dw_hh  = (const float*)d_in[7];
    const float* db_ih  = (const float*)d_in[8];
    const float* db_hh  = (const float*)d_in[9];
    const float* out_w  = (const float*)d_in[10];
    const float* out_b  = (const float*)d_in[11];
    const float* wa     = (const float*)d_in[12];
    float* out = (float*)d_out;

    int write_ids = (out_size >= T * V + T) ? 1 : 0;

    static cudaStream_t s2 = nullptr;
    static cudaEvent_t evFork = nullptr, evJoin = nullptr;
    if (!s2) {
        cudaStreamCreateWithFlags(&s2, cudaStreamNonBlocking);
        cudaEventCreateWithFlags(&evFork, cudaEventDisableTiming);
        cudaEventCreateWithFlags(&evJoin, cudaEventDisableTiming);
    }

    k_init<<<256, 256>>>(seq, out, out_size);
    for (int s = 0; s < T; s++)
        k_lstm_enc<<<H / 2, 256>>>(ew_ih, ew_hh, eb_ih, eb_hh, embeds, s, s & 1);

    k_qattn<<<32, 256>>>(wa, 0);

    for (int d = 0; d < T; d++) {
        int bi = d & 1;
        k_lstm_dec<<<H / 2, 256>>>(dw_ih, dw_hh, db_ih, db_hh, bi);
        if (d + 1 < T) {
            cudaEventRecord(evFork, 0);
            cudaStreamWaitEvent(s2, evFork, 0);
            k_qattn<<<32, 256, 0, s2>>>(wa, (d + 1) & 1);
            cudaEventRecord(evJoin, s2);
        }
        if (d == 0)
            k_logits_conv<<<NLB, 256>>>(out_w, out_b, 1 - bi,
                                        out + (size_t)d * V,
                                        embeds, out + (size_t)T * V,
                                        write_ids, d);
        else
            k_logits16<<<NLB, 256>>>(out_w, out_b, 1 - bi,
                                     out + (size_t)d * V,
                                     embeds, out + (size_t)T * V,
                                     write_ids, d);
        if (d + 1 < T) cudaStreamWaitEvent(0, evJoin, 0);
    }
}

// round 7
// speedup vs baseline: 1.0598x; 1.0598x over previous
#include <cuda_runtime.h>
#include <math.h>

#define V 50257
#define H 1024
#define T 10
#define LROWS 16
#define NLB ((V + LROWS - 1) / LROWS)   // 3142 logits blocks
#define NB_ENC 512

// ---------------- device scratch (no allocations allowed) ----------------
__device__ __align__(16) float g_h[2][H];
__device__ __align__(16) float g_c[2][H];
__device__ __align__(16) float g_enc[T * H];
__device__ __align__(16) float g_prev[H];
__device__ __align__(16) float g_q[H];
__device__ __align__(16) float g_ctx[H];
__device__ int   g_tok[T];
__device__ float g_pval[NLB + 32];
__device__ int   g_pidx[NLB + 32];
__device__ unsigned int g_cnt1;
__device__ unsigned int g_cnt2;
__device__ unsigned int g_arrive;   // persistent-kernel grid barrier
__device__ unsigned int g_gen;

__device__ __forceinline__ float sigm(float x) { return 1.f / (1.f + expf(-x)); }
__device__ __forceinline__ float dot4(float4 a, float4 b) {
    return a.x * b.x + a.y * b.y + a.z * b.z + a.w * b.w;
}

// ---- spin grid barrier (all NB blocks co-resident; generation counter) ---
__device__ __forceinline__ void grid_barrier(unsigned nb) {
    __threadfence();
    __syncthreads();
    if (threadIdx.x == 0) {
        unsigned gen = atomicAdd(&g_gen, 0u);
        if (atomicAdd(&g_arrive, 1u) == nb - 1) {
            g_arrive = 0;
            __threadfence();
            atomicExch(&g_gen, gen + 1);
        } else {
            while (atomicAdd(&g_gen, 0u) == gen) {}
        }
    }
    __syncthreads();
    __threadfence();
}

// ---------------- init: decode tokens (int64 vs int32), zero state/out ---
__global__ void k_init(const void* __restrict__ seq_raw,
                       float* __restrict__ out, int out_size) {
    int tid = blockIdx.x * blockDim.x + threadIdx.x;
    if (tid == 0) {
        const long long* s64 = (const long long*)seq_raw;
        bool ok64 = true;
        for (int i = 0; i < T; i++) {
            long long v = s64[i];
            if (v < 0 || v >= V) { ok64 = false; break; }
        }
        const int* s32 = (const int*)seq_raw;
        for (int i = 0; i < T; i++) g_tok[i] = ok64 ? (int)s64[i] : s32[i];
        g_cnt1 = 0; g_cnt2 = 0; g_arrive = 0;
    }
    int stride = gridDim.x * blockDim.x;
    for (int i = tid; i < H; i += stride) {
        g_h[0][i] = 0.f; g_c[0][i] = 0.f; g_prev[i] = 0.f;
    }
    for (int i = tid; i < out_size; i += stride) out[i] = 0.f;
}

// ------- persistent encoder: all T steps in ONE launch -------------------
// 512 blocks x 256 threads, 2 units/block, warp-per-gate. Weights (32MB =
// 216KB/SM) become L1-resident after step 0; steps separated by grid barrier.
__global__ void __launch_bounds__(256, 4) k_enc_persist(
        const float* __restrict__ w_ih, const float* __restrict__ w_hh,
        const float* __restrict__ b_ih, const float* __restrict__ b_hh,
        const float* __restrict__ embeds) {
    int tid  = threadIdx.x;
    int warp = tid >> 5;
    int lane = tid & 31;
    int j    = blockIdx.x * 2 + (warp >> 2);
    int gate = warp & 3;

    const float4* wi = (const float4*)w_ih + (size_t)(gate * H + j) * 256;
    const float4* wh = (const float4*)w_hh + (size_t)(gate * H + j) * 256;

    __shared__ float s[8];

    for (int step = 0; step < T; step++) {
        int bi = step & 1;
        const float4* x4 = (const float4*)(embeds + (size_t)g_tok[step] * H);
        const float4* h4 = (const float4*)g_h[bi];

        float acc = 0.f;
#pragma unroll
        for (int i = 0; i < 8; i++) {
            int k = lane + 32 * i;
            acc += dot4(wi[k], x4[k]) + dot4(wh[k], h4[k]);
        }
        for (int off = 16; off > 0; off >>= 1)
            acc += __shfl_down_sync(0xffffffffu, acc, off);
        if (lane == 0) s[warp] = acc;
        __syncthreads();
        if (tid < 2) {
            int u = blockIdx.x * 2 + tid;
            float gi = s[tid * 4 + 0] + b_ih[u]         + b_hh[u];
            float gf = s[tid * 4 + 1] + b_ih[H + u]     + b_hh[H + u];
            float gg = s[tid * 4 + 2] + b_ih[2 * H + u] + b_hh[2 * H + u];
            float go = s[tid * 4 + 3] + b_ih[3 * H + u] + b_hh[3 * H + u];
            float i_ = sigm(gi), f_ = sigm(gf), g_ = tanhf(gg), o_ = sigm(go);
            float cn = f_ * g_c[bi][u] + i_ * g_;
            float hn = o_ * tanhf(cn);
            g_c[1 - bi][u] = cn;
            g_h[1 - bi][u] = hn;
            g_enc[step * H + u] = hn;
        }
        grid_barrier(NB_ENC);   // includes the syncthreads protecting s[]
    }
}

// ---------------- q = wa^T h, then last block does softmax+ctx -----------
__global__ void k_qattn(const float* __restrict__ wa, int bi) {
    int tid  = threadIdx.x;
    int lane = tid & 31;
    int warp = tid >> 5;
    int col  = blockIdx.x * 32 + lane;
    const float* h = g_h[bi];

    float acc = 0.f;
    for (int i = warp; i < H; i += 8) acc += h[i] * wa[(size_t)i * H + col];
    __shared__ float s[256];
    s[tid] = acc;
    __syncthreads();
    for (int off = 128; off >= 32; off >>= 1) {
        if (tid < off) s[tid] += s[tid + off];
        __syncthreads();
    }
    if (tid < 32) g_q[col] = s[tid];

    __shared__ int s_last;
    __threadfence();
    if (tid == 0) s_last = (atomicAdd(&g_cnt1, 1u) == gridDim.x - 1);
    __syncthreads();
    if (!s_last) return;
    if (tid == 0) g_cnt1 = 0;

    float at[T];
#pragma unroll
    for (int t = 0; t < T; t++) at[t] = 0.f;
    for (int k = tid; k < H; k += 256) {
        float qv = g_q[k];
#pragma unroll
        for (int t = 0; t < T; t++) at[t] += qv * g_enc[t * H + k];
    }
#pragma unroll
    for (int t = 0; t < T; t++)
        for (int off = 16; off > 0; off >>= 1)
            at[t] += __shfl_down_sync(0xffffffffu, at[t], off);
    __shared__ float s2[T * 8];
    if (lane == 0) {
#pragma unroll
        for (int t = 0; t < T; t++) s2[t * 8 + warp] = at[t];
    }
    __syncthreads();
    __shared__ float sa[T];
    if (tid == 0) {
        float sc[T];
        float m = -INFINITY;
#pragma unroll
        for (int t = 0; t < T; t++) {
            float v = 0.f;
#pragma unroll
            for (int w = 0; w < 8; w++) v += s2[t * 8 + w];
            sc[t] = v;
            m = fmaxf(m, v);
        }
        float sum = 0.f;
#pragma unroll
        for (int t = 0; t < T; t++) { float e = expf(sc[t] - m); sa[t] = e; sum += e; }
#pragma unroll
        for (int t = 0; t < T; t++) sa[t] /= sum;
    }
    __syncthreads();
    for (int k = tid; k < H; k += 256) {
        float v = 0.f;
#pragma unroll
        for (int t = 0; t < T; t++) v += sa[t] * g_enc[t * H + k];
        g_ctx[k] = v;
    }
}

// ------- decoder LSTM: 1 unit/block (grid 1024), 2 warps per gate --------
// Row = [w_ih row | w_hh row] = 768 float4; warp (gate, half) covers 384.
__global__ void k_lstm_dec(const float* __restrict__ w_ih,  // (4H, 2H)
                           const float* __restrict__ w_hh,  // (4H, H)
                           const float* __restrict__ b_ih,
                           const float* __restrict__ b_hh,
                           int bi) {
    int tid  = threadIdx.x;
    int warp = tid >> 5;
    int lane = tid & 31;
    int j    = blockIdx.x;
    int gate = warp >> 1;
    int half = warp & 1;

    const float4* wi = (const float4*)w_ih + (size_t)(gate * H + j) * 512;
    const float4* wh = (const float4*)w_hh + (size_t)(gate * H + j) * 256;
    const float4* p4 = (const float4*)g_prev;
    const float4* c4 = (const float4*)g_ctx;
    const float4* h4 = (const float4*)g_h[bi];

    float acc = 0.f;
    if (half == 0) {
        // k = lane + 32*i, i in [0,12): i<8 -> relu(prev), else ctx
#pragma unroll
        for (int i = 0; i < 8; i++) {
            int k = lane + 32 * i;
            float4 v = p4[k];
            v.x = fmaxf(v.x, 0.f); v.y = fmaxf(v.y, 0.f);
            v.z = fmaxf(v.z, 0.f); v.w = fmaxf(v.w, 0.f);
            acc += dot4(wi[k], v);
        }
#pragma unroll
        for (int i = 8; i < 12; i++) {
            int k = lane + 32 * i;
            acc += dot4(wi[k], c4[k - 256]);
        }
    } else {
        // k = 384 + lane + 32*i, i in [0,12): i<4 -> ctx, else w_hh/h
#pragma unroll
        for (int i = 0; i < 4; i++) {
            int k = 384 + lane + 32 * i;
            acc += dot4(wi[k], c4[k - 256]);
        }
#pragma unroll
        for (int i = 4; i < 12; i++) {
            int k = 384 + lane + 32 * i - 512;   // 0..255 into w_hh/h
            acc += dot4(wh[k], h4[k]);
        }
    }
    for (int off = 16; off > 0; off >>= 1)
        acc += __shfl_down_sync(0xffffffffu, acc, off);

    __shared__ float s[8];
    if (lane == 0) s[warp] = acc;
    __syncthreads();
    if (tid == 0) {
        float gi = s[0] + s[1] + b_ih[j]         + b_hh[j];
        float gf = s[2] + s[3] + b_ih[H + j]     + b_hh[H + j];
        float gg = s[4] + s[5] + b_ih[2 * H + j] + b_hh[2 * H + j];
        float go = s[6] + s[7] + b_ih[3 * H + j] + b_hh[3 * H + j];
        float i_ = sigm(gi), f_ = sigm(gf), g_ = tanhf(gg), o_ = sigm(go);
        float cn = f_ * g_c[bi][j] + i_ * g_;
        float hn = o_ * tanhf(cn);
        g_c[1 - bi][j] = cn;
        g_h[1 - bi][j] = hn;
    }
}

// ---------------- logits (R3-proven): 2 rows/warp, __ldcs, fused argmax --
__global__ void k_logits(const float* __restrict__ out_w,
                         const float* __restrict__ out_b,
                         int hb, float* __restrict__ out,
                         const float* __restrict__ embeds,
                         float* __restrict__ out_ids, int write_ids, int step) {
    int tid  = threadIdx.x;
    int lane = tid & 31;
    int warp = tid >> 5;                 // 8 warps, 2 rows each
    int r0 = blockIdx.x * LROWS + warp * 2;
    int r1 = r0 + 1;

    const float4* h4 = (const float4*)g_h[hb];
    float4 hv[8];
#pragma unroll
    for (int i = 0; i < 8; i++) hv[i] = h4[lane + 32 * i];

    float t0 = 0.f, t1 = 0.f;
    if (r0 < V) {
        const float4* w0 = (const float4*)(out_w + (size_t)r0 * H);
#pragma unroll
        for (int i = 0; i < 8; i++) t0 += dot4(__ldcs(w0 + lane + 32 * i), hv[i]);
    }
    if (r1 < V) {
        const float4* w1 = (const float4*)(out_w + (size_t)r1 * H);
#pragma unroll
        for (int i = 0; i < 8; i++) t1 += dot4(__ldcs(w1 + lane + 32 * i), hv[i]);
    }
    for (int off = 16; off > 0; off >>= 1) {
        t0 += __shfl_down_sync(0xffffffffu, t0, off);
        t1 += __shfl_down_sync(0xffffffffu, t1, off);
    }

    __shared__ float bv[16];
    __shared__ int   bix[16];
    __shared__ int   s_last;
    if (lane == 0) {
        float l0 = -INFINITY, l1 = -INFINITY;
        if (r0 < V) { l0 = t0 + out_b[r0]; __stcs(out + r0, l0); }
        if (r1 < V) { l1 = t1 + out_b[r1]; __stcs(out + r1, l1); }
        bv[warp * 2] = l0;     bix[warp * 2] = r0;
        bv[warp * 2 + 1] = l1; bix[warp * 2 + 1] = r1;
    }
    __syncthreads();
    if (tid == 0) {
        float best = bv[0]; int bj = bix[0];
#pragma unroll
        for (int w = 1; w < 16; w++)
            if (bv[w] > best) { best = bv[w]; bj = bix[w]; }
        g_pval[blockIdx.x] = best;
        g_pidx[blockIdx.x] = bj;
        __threadfence();
        s_last = (atomicAdd(&g_cnt2, 1u) == gridDim.x - 1);
    }
    __syncthreads();
    if (!s_last) return;
    if (tid == 0) g_cnt2 = 0;

    // -------- final argmax (first-max, matches jnp.argmax) + gather ------
    float best = -INFINITY;
    int bidx = 0x7fffffff;
    int nb = gridDim.x;
    for (int i = tid; i < nb; i += 256) {
        float v = g_pval[i]; int ix = g_pidx[i];
        if (v > best || (v == best && ix < bidx)) { best = v; bidx = ix; }
    }
    __shared__ float sv[256];
    __shared__ int   si[256];
    sv[tid] = best; si[tid] = bidx;
    __syncthreads();
    for (int off = 128; off > 0; off >>= 1) {
        if (tid < off) {
            float v2 = sv[tid + off]; int i2 = si[tid + off];
            if (v2 > sv[tid] || (v2 == sv[tid] && i2 < si[tid])) {
                sv[tid] = v2; si[tid] = i2;
            }
        }
        __syncthreads();
    }
    int idx = si[0];
    for (int k = tid; k < H; k += 256)
        g_prev[k] = embeds[(size_t)idx * H + k];
    if (tid == 0 && write_ids) out_ids[step] = (float)idx;
}

// ---------------- launch ---------------------------------------------------
extern "C" void kernel_launch(void* const* d_in, const int* in_sizes, int n_in,
                              void* d_out, int out_size) {
    const void*  seq    = d_in[0];
    const float* embeds = (const float*)d_in[1];
    const float* ew_ih  = (const float*)d_in[2];
    const float* ew_hh  = (const float*)d_in[3];
    const float* eb_ih  = (const float*)d_in[4];
    const float* eb_hh  = (const float*)d_in[5];
    const float* dw_ih  = (const float*)d_in[6];
    const float* dw_hh  = (const float*)d_in[7];
    const float* db_ih  = (const float*)d_in[8];
    const float* db_hh  = (const float*)d_in[9];
    const float* out_w  = (const float*)d_in[10];
    const float* out_b  = (const float*)d_in[11];
    const float* wa     = (const float*)d_in[12];
    float* out = (float*)d_out;

    int write_ids = (out_size >= T * V + T) ? 1 : 0;

    static cudaStream_t s2 = nullptr;
    static cudaEvent_t evFork = nullptr, evJoin = nullptr;
    if (!s2) {
        cudaStreamCreateWithFlags(&s2, cudaStreamNonBlocking);
        cudaEventCreateWithFlags(&evFork, cudaEventDisableTiming);
        cudaEventCreateWithFlags(&evJoin, cudaEventDisableTiming);
    }

    k_init<<<256, 256>>>(seq, out, out_size);

    // all 10 encoder steps in one persistent launch
    k_enc_persist<<<NB_ENC, 256>>>(ew_ih, ew_hh, eb_ih, eb_hh, embeds);

    // decoder; qattn(d+1) overlaps logits(d) on side stream
    k_qattn<<<32, 256>>>(wa, 0);
    for (int d = 0; d < T; d++) {
        int bi = d & 1;                 // current h/c buffer
        k_lstm_dec<<<H, 256>>>(dw_ih, dw_hh, db_ih, db_hh, bi);
        if (d + 1 < T) {
            cudaEventRecord(evFork, 0);
            cudaStreamWaitEvent(s2, evFork, 0);
            k_qattn<<<32, 256, 0, s2>>>(wa, (d + 1) & 1);
            cudaEventRecord(evJoin, s2);
        }
        k_logits<<<NLB, 256>>>(out_w, out_b, 1 - bi,
                               out + (size_t)d * V,
                               embeds, out + (size_t)T * V,
                               write_ids, d);
        if (d + 1 < T) cudaStreamWaitEvent(0, evJoin, 0);
    }
}

// round 8
// speedup vs baseline: 1.1626x; 1.0971x over previous
#include <cuda_runtime.h>
#include <math.h>

#define V 50257
#define H 1024
#define T 10
#define LROWS 16
#define NLB ((V + LROWS - 1) / LROWS)   // 3142 logits blocks

// ---------------- device scratch (no allocations allowed) ----------------
__device__ __align__(16) float g_h[2][H];
__device__ __align__(16) float g_c[2][H];
__device__ __align__(16) float g_enc[T * H];
__device__ __align__(16) float g_prev[H];
__device__ __align__(16) float g_q[H];
__device__ __align__(16) float g_ctx[H];
__device__ __align__(16) float g_gate[4 * H];  // partial gate sums (ctx+h terms)
__device__ int   g_tok[T];
__device__ float g_pval[NLB + 32];
__device__ int   g_pidx[NLB + 32];
__device__ unsigned int g_cnt1;
__device__ unsigned int g_cnt2;

__device__ __forceinline__ float sigm(float x) { return 1.f / (1.f + expf(-x)); }
__device__ __forceinline__ float dot4(float4 a, float4 b) {
    return a.x * b.x + a.y * b.y + a.z * b.z + a.w * b.w;
}

// ---------------- init: decode tokens (int64 vs int32), zero state/out ---
__global__ void k_init(const void* __restrict__ seq_raw,
                       float* __restrict__ out, int out_size) {
    int tid = blockIdx.x * blockDim.x + threadIdx.x;
    if (tid == 0) {
        const long long* s64 = (const long long*)seq_raw;
        bool ok64 = true;
        for (int i = 0; i < T; i++) {
            long long v = s64[i];
            if (v < 0 || v >= V) { ok64 = false; break; }
        }
        const int* s32 = (const int*)seq_raw;
        for (int i = 0; i < T; i++) g_tok[i] = ok64 ? (int)s64[i] : s32[i];
        g_cnt1 = 0; g_cnt2 = 0;
    }
    int stride = gridDim.x * blockDim.x;
    for (int i = tid; i < H; i += stride) {
        g_h[0][i] = 0.f; g_c[0][i] = 0.f; g_prev[i] = 0.f;
    }
    for (int i = tid; i < out_size; i += stride) out[i] = 0.f;
}

// ---------------- encoder LSTM: 2 units/block, warp-per-gate (R3) --------
__global__ void k_lstm_enc(const float* __restrict__ w_ih,
                           const float* __restrict__ w_hh,
                           const float* __restrict__ b_ih,
                           const float* __restrict__ b_hh,
                           const float* __restrict__ embeds,
                           int step, int bi) {
    int tid  = threadIdx.x;
    int warp = tid >> 5;
    int lane = tid & 31;
    int j    = blockIdx.x * 2 + (warp >> 2);
    int gate = warp & 3;

    const float4* x4 = (const float4*)(embeds + (size_t)g_tok[step] * H);
    const float4* h4 = (const float4*)g_h[bi];
    const float4* wi = (const float4*)w_ih + (size_t)(gate * H + j) * 256;
    const float4* wh = (const float4*)w_hh + (size_t)(gate * H + j) * 256;

    float acc = 0.f;
#pragma unroll
    for (int i = 0; i < 8; i++) {
        int k = lane + 32 * i;
        acc += dot4(wi[k], x4[k]) + dot4(wh[k], h4[k]);
    }
    for (int off = 16; off > 0; off >>= 1)
        acc += __shfl_down_sync(0xffffffffu, acc, off);

    __shared__ float s[8];
    if (lane == 0) s[warp] = acc;
    __syncthreads();
    if (tid < 2) {
        int u = blockIdx.x * 2 + tid;
        float gi = s[tid * 4 + 0] + b_ih[u]         + b_hh[u];
        float gf = s[tid * 4 + 1] + b_ih[H + u]     + b_hh[H + u];
        float gg = s[tid * 4 + 2] + b_ih[2 * H + u] + b_hh[2 * H + u];
        float go = s[tid * 4 + 3] + b_ih[3 * H + u] + b_hh[3 * H + u];
        float i_ = sigm(gi), f_ = sigm(gf), g_ = tanhf(gg), o_ = sigm(go);
        float cn = f_ * g_c[bi][u] + i_ * g_;
        float hn = o_ * tanhf(cn);
        g_c[1 - bi][u] = cn;
        g_h[1 - bi][u] = hn;
        g_enc[step * H + u] = hn;
    }
}

// ---------------- q = wa^T h, then last block does softmax+ctx (R3) ------
__global__ void k_qattn(const float* __restrict__ wa, int bi) {
    int tid  = threadIdx.x;
    int lane = tid & 31;
    int warp = tid >> 5;
    int col  = blockIdx.x * 32 + lane;
    const float* h = g_h[bi];

    float acc = 0.f;
    for (int i = warp; i < H; i += 8) acc += h[i] * wa[(size_t)i * H + col];
    __shared__ float s[256];
    s[tid] = acc;
    __syncthreads();
    for (int off = 128; off >= 32; off >>= 1) {
        if (tid < off) s[tid] += s[tid + off];
        __syncthreads();
    }
    if (tid < 32) g_q[col] = s[tid];

    __shared__ int s_last;
    __threadfence();
    if (tid == 0) s_last = (atomicAdd(&g_cnt1, 1u) == gridDim.x - 1);
    __syncthreads();
    if (!s_last) return;
    if (tid == 0) g_cnt1 = 0;

    float at[T];
#pragma unroll
    for (int t = 0; t < T; t++) at[t] = 0.f;
    for (int k = tid; k < H; k += 256) {
        float qv = g_q[k];
#pragma unroll
        for (int t = 0; t < T; t++) at[t] += qv * g_enc[t * H + k];
    }
#pragma unroll
    for (int t = 0; t < T; t++)
        for (int off = 16; off > 0; off >>= 1)
            at[t] += __shfl_down_sync(0xffffffffu, at[t], off);
    __shared__ float s2[T * 8];
    if (lane == 0) {
#pragma unroll
        for (int t = 0; t < T; t++) s2[t * 8 + warp] = at[t];
    }
    __syncthreads();
    __shared__ float sa[T];
    if (tid == 0) {
        float sc[T];
        float m = -INFINITY;
#pragma unroll
        for (int t = 0; t < T; t++) {
            float v = 0.f;
#pragma unroll
            for (int w = 0; w < 8; w++) v += s2[t * 8 + w];
            sc[t] = v;
            m = fmaxf(m, v);
        }
        float sum = 0.f;
#pragma unroll
        for (int t = 0; t < T; t++) { float e = expf(sc[t] - m); sa[t] = e; sum += e; }
#pragma unroll
        for (int t = 0; t < T; t++) sa[t] /= sum;
    }
    __syncthreads();
    for (int k = tid; k < H; k += 256) {
        float v = 0.f;
#pragma unroll
        for (int t = 0; t < T; t++) v += sa[t] * g_enc[t * H + k];
        g_ctx[k] = v;
    }
}

// ------- decoder part 1 (prev-independent): g_gate = Wih[:,H:]ctx + Whh h -
// Runs on side stream, overlapped with the previous step's logits.
__global__ void k_dec_pre(const float* __restrict__ w_ih,  // (4H, 2H)
                          const float* __restrict__ w_hh,  // (4H, H)
                          int bi) {
    int tid  = threadIdx.x;
    int warp = tid >> 5;
    int lane = tid & 31;
    int j    = blockIdx.x * 2 + (warp >> 2);
    int gate = warp & 3;

    const float4* h4 = (const float4*)g_h[bi];
    const float4* c4 = (const float4*)g_ctx;
    const float4* wi = (const float4*)w_ih + (size_t)(gate * H + j) * 512 + 256;
    const float4* wh = (const float4*)w_hh + (size_t)(gate * H + j) * 256;

    float acc = 0.f;
#pragma unroll
    for (int i = 0; i < 8; i++) {
        int k = lane + 32 * i;
        acc += dot4(wi[k], c4[k]);
        acc += dot4(wh[k], h4[k]);
    }
    for (int off = 16; off > 0; off >>= 1)
        acc += __shfl_down_sync(0xffffffffu, acc, off);
    if (lane == 0) g_gate[gate * H + j] = acc;
}

// ------- decoder part 2 (prev term + cell update) -------------------------
__global__ void k_dec_fin(const float* __restrict__ w_ih,  // (4H, 2H)
                          const float* __restrict__ b_ih,
                          const float* __restrict__ b_hh,
                          int bi) {
    int tid  = threadIdx.x;
    int warp = tid >> 5;
    int lane = tid & 31;
    int j    = blockIdx.x * 2 + (warp >> 2);
    int gate = warp & 3;

    const float4* p4 = (const float4*)g_prev;
    const float4* wi = (const float4*)w_ih + (size_t)(gate * H + j) * 512;

    float acc = 0.f;
#pragma unroll
    for (int i = 0; i < 8; i++) {
        int k = lane + 32 * i;
        float4 v = p4[k];
        v.x = fmaxf(v.x, 0.f); v.y = fmaxf(v.y, 0.f);
        v.z = fmaxf(v.z, 0.f); v.w = fmaxf(v.w, 0.f);
        acc += dot4(wi[k], v);
    }
    for (int off = 16; off > 0; off >>= 1)
        acc += __shfl_down_sync(0xffffffffu, acc, off);

    __shared__ float s[8];
    if (lane == 0) s[warp] = acc;
    __syncthreads();
    if (tid < 2) {
        int u = blockIdx.x * 2 + tid;
        float gi = s[tid * 4 + 0] + g_gate[0 * H + u] + b_ih[u]         + b_hh[u];
        float gf = s[tid * 4 + 1] + g_gate[1 * H + u] + b_ih[H + u]     + b_hh[H + u];
        float gg = s[tid * 4 + 2] + g_gate[2 * H + u] + b_ih[2 * H + u] + b_hh[2 * H + u];
        float go = s[tid * 4 + 3] + g_gate[3 * H + u] + b_ih[3 * H + u] + b_hh[3 * H + u];
        float i_ = sigm(gi), f_ = sigm(gf), g_ = tanhf(gg), o_ = sigm(go);
        float cn = f_ * g_c[bi][u] + i_ * g_;
        float hn = o_ * tanhf(cn);
        g_c[1 - bi][u] = cn;
        g_h[1 - bi][u] = hn;
    }
}

// ---------------- logits (R3-proven): 2 rows/warp, __ldcs, fused argmax --
__global__ void k_logits(const float* __restrict__ out_w,
                         const float* __restrict__ out_b,
                         int hb, float* __restrict__ out,
                         const float* __restrict__ embeds,
                         float* __restrict__ out_ids, int write_ids, int step) {
    int tid  = threadIdx.x;
    int lane = tid & 31;
    int warp = tid >> 5;                 // 8 warps, 2 rows each
    int r0 = blockIdx.x * LROWS + warp * 2;
    int r1 = r0 + 1;

    const float4* h4 = (const float4*)g_h[hb];
    float4 hv[8];
#pragma unroll
    for (int i = 0; i < 8; i++) hv[i] = h4[lane + 32 * i];

    float t0 = 0.f, t1 = 0.f;
    if (r0 < V) {
        const float4* w0 = (const float4*)(out_w + (size_t)r0 * H);
#pragma unroll
        for (int i = 0; i < 8; i++) t0 += dot4(__ldcs(w0 + lane + 32 * i), hv[i]);
    }
    if (r1 < V) {
        const float4* w1 = (const float4*)(out_w + (size_t)r1 * H);
#pragma unroll
        for (int i = 0; i < 8; i++) t1 += dot4(__ldcs(w1 + lane + 32 * i), hv[i]);
    }
    for (int off = 16; off > 0; off >>= 1) {
        t0 += __shfl_down_sync(0xffffffffu, t0, off);
        t1 += __shfl_down_sync(0xffffffffu, t1, off);
    }

    __shared__ float bv[16];
    __shared__ int   bix[16];
    __shared__ int   s_last;
    if (lane == 0) {
        float l0 = -INFINITY, l1 = -INFINITY;
        if (r0 < V) { l0 = t0 + out_b[r0]; __stcs(out + r0, l0); }
        if (r1 < V) { l1 = t1 + out_b[r1]; __stcs(out + r1, l1); }
        bv[warp * 2] = l0;     bix[warp * 2] = r0;
        bv[warp * 2 + 1] = l1; bix[warp * 2 + 1] = r1;
    }
    __syncthreads();
    if (tid == 0) {
        float best = bv[0]; int bj = bix[0];
#pragma unroll
        for (int w = 1; w < 16; w++)
            if (bv[w] > best) { best = bv[w]; bj = bix[w]; }
        g_pval[blockIdx.x] = best;
        g_pidx[blockIdx.x] = bj;
        __threadfence();
        s_last = (atomicAdd(&g_cnt2, 1u) == gridDim.x - 1);
    }
    __syncthreads();
    if (!s_last) return;
    if (tid == 0) g_cnt2 = 0;

    // -------- final argmax (first-max, matches jnp.argmax) + gather ------
    float best = -INFINITY;
    int bidx = 0x7fffffff;
    int nb = gridDim.x;
    for (int i = tid; i < nb; i += 256) {
        float v = g_pval[i]; int ix = g_pidx[i];
        if (v > best || (v == best && ix < bidx)) { best = v; bidx = ix; }
    }
    __shared__ float sv[256];
    __shared__ int   si[256];
    sv[tid] = best; si[tid] = bidx;
    __syncthreads();
    for (int off = 128; off > 0; off >>= 1) {
        if (tid < off) {
            float v2 = sv[tid + off]; int i2 = si[tid + off];
            if (v2 > sv[tid] || (v2 == sv[tid] && i2 < si[tid])) {
                sv[tid] = v2; si[tid] = i2;
            }
        }
        __syncthreads();
    }
    int idx = si[0];
    for (int k = tid; k < H; k += 256)
        g_prev[k] = embeds[(size_t)idx * H + k];
    if (tid == 0 && write_ids) out_ids[step] = (float)idx;
}

// ---------------- launch ---------------------------------------------------
extern "C" void kernel_launch(void* const* d_in, const int* in_sizes, int n_in,
                              void* d_out, int out_size) {
    const void*  seq    = d_in[0];
    const float* embeds = (const float*)d_in[1];
    const float* ew_ih  = (const float*)d_in[2];
    const float* ew_hh  = (const float*)d_in[3];
    const float* eb_ih  = (const float*)d_in[4];
    const float* eb_hh  = (const float*)d_in[5];
    const float* dw_ih  = (const float*)d_in[6];
    const float* dw_hh  = (const float*)d_in[7];
    const float* db_ih  = (const float*)d_in[8];
    const float* db_hh  = (const float*)d_in[9];
    const float* out_w  = (const float*)d_in[10];
    const float* out_b  = (const float*)d_in[11];
    const float* wa     = (const float*)d_in[12];
    float* out = (float*)d_out;

    int write_ids = (out_size >= T * V + T) ? 1 : 0;

    static cudaStream_t s2 = nullptr;
    static cudaEvent_t evFork = nullptr, evJoin = nullptr;
    if (!s2) {
        int loPri, hiPri;
        cudaDeviceGetStreamPriorityRange(&loPri, &hiPri);
        cudaStreamCreateWithPriority(&s2, cudaStreamNonBlocking, hiPri);
        cudaEventCreateWithFlags(&evFork, cudaEventDisableTiming);
        cudaEventCreateWithFlags(&evJoin, cudaEventDisableTiming);
    }

    k_init<<<256, 256>>>(seq, out, out_size);

    // encoder: step s reads buf (s&1), writes buf 1-(s&1); final h in buf 0
    for (int s = 0; s < T; s++)
        k_lstm_enc<<<H / 2, 256>>>(ew_ih, ew_hh, eb_ih, eb_hh, embeds, s, s & 1);

    // step 0 front end (nothing to overlap with yet)
    k_qattn<<<32, 256>>>(wa, 0);
    k_dec_pre<<<H / 2, 256>>>(dw_ih, dw_hh, 0);
    k_dec_fin<<<H / 2, 256>>>(dw_ih, db_ih, db_hh, 0);

    for (int d = 0; d < T; d++) {
        int bi = d & 1;
        // overlap with logits(d): qattn(d+1) + dec_pre(d+1) on side stream
        if (d + 1 < T) {
            cudaEventRecord(evFork, 0);          // after dec_fin(d)
            cudaStreamWaitEvent(s2, evFork, 0);
            k_qattn<<<32, 256, 0, s2>>>(wa, (d + 1) & 1);
            k_dec_pre<<<H / 2, 256, 0, s2>>>(dw_ih, dw_hh, (d + 1) & 1);
            cudaEventRecord(evJoin, s2);
        }
        k_logits<<<NLB, 256>>>(out_w, out_b, 1 - bi,
                               out + (size_t)d * V,
                               embeds, out + (size_t)T * V,
                               write_ids, d);
        if (d + 1 < T) {
            cudaStreamWaitEvent(0, evJoin, 0);
            k_dec_fin<<<H / 2, 256>>>(dw_ih, db_ih, db_hh, (d + 1) & 1);
        }
    }
}